// round 13
// baseline (speedup 1.0000x reference)
#include <cuda_runtime.h>
#include <cuda_bf16.h>
#include <math.h>
#include <string.h>

// Problem constants (fixed by the dataset)
#define EMB     512
#define HIDDEN  1024
#define HALF_H  512
#define BATCH   256
#define SEQLEN  512
#define NTOK    (BATCH * SEQLEN)   // 131072
#define KP      1536               // 3 * 512 packed-K for split-bf16 GEMMs

#define NCTA    128
#define RTHR    320                // recurrence: 8 MMA warps + 2 comm warps

// ---------------------------------------------------------------------------
// Device globals (allocation-free scratch)
// h / h1 exchange buffers are chunk-contiguous per producer CTA:
//   g_h_bf16 : [8 groups][16 producers][32 rows][64 cols]  (rows XOR-swizzled)
//   g_h1_bf16: [8 groups][16 producers][32 rows][32 cols]  (rows XOR-swizzled)
// ---------------------------------------------------------------------------
__device__ unsigned short g_a1p[(size_t)NTOK * KP];    // packed seq   [M][1536]
__device__ unsigned short g_hidp[(size_t)NTOK * KP];   // packed hid1  [M][1536]
__device__ unsigned short g_w1xp[HALF_H * KP];         // packed w1x   [512][1536] (n-major)
__device__ unsigned short g_w2xp[HIDDEN * KP];         // packed w2x   [1024][1536] (n-major)
__device__ unsigned short g_h_bf16[BATCH * HIDDEN];
__device__ unsigned short g_h1_bf16[BATCH * HALF_H];
__device__ volatile unsigned g_ggen[8 * 32];           // init barrier gen
__device__ unsigned g_gcnt[8 * 32];                    // init barrier count
__device__ volatile unsigned g_hflag[8][16 * 32];      // h ready flags (128B apart)
__device__ volatile unsigned g_h1flag[8][16 * 32];     // h1 ready flags

// ---------------------------------------------------------------------------
// Helpers
// ---------------------------------------------------------------------------
static __device__ __forceinline__ unsigned smem_u32(const void* p) {
    unsigned a;
    asm("{ .reg .u64 t; cvta.to.shared.u64 t, %1; cvt.u32.u64 %0, t; }"
        : "=r"(a) : "l"(p));
    return a;
}

static __device__ __forceinline__ void ldsm_x4(unsigned& r0, unsigned& r1,
                                               unsigned& r2, unsigned& r3,
                                               unsigned addr) {
    asm volatile("ldmatrix.sync.aligned.m8n8.x4.shared.b16 {%0,%1,%2,%3}, [%4];"
                 : "=r"(r0), "=r"(r1), "=r"(r2), "=r"(r3) : "r"(addr));
}

static __device__ __forceinline__ void ldsm_x2(unsigned& r0, unsigned& r1,
                                               unsigned addr) {
    asm volatile("ldmatrix.sync.aligned.m8n8.x2.shared.b16 {%0,%1}, [%2];"
                 : "=r"(r0), "=r"(r1) : "r"(addr));
}

static __device__ __forceinline__ void mma_bf16(float& c0, float& c1, float& c2, float& c3,
                                                unsigned a0, unsigned a1, unsigned a2, unsigned a3,
                                                unsigned b0, unsigned b1) {
    asm volatile("mma.sync.aligned.m16n8k16.row.col.f32.bf16.bf16.f32 "
                 "{%0,%1,%2,%3}, {%4,%5,%6,%7}, {%8,%9}, {%0,%1,%2,%3};"
                 : "+f"(c0), "+f"(c1), "+f"(c2), "+f"(c3)
                 : "r"(a0), "r"(a1), "r"(a2), "r"(a3), "r"(b0), "r"(b1));
}

static __device__ __forceinline__ unsigned pack_bf16(float x, float y) {
    __nv_bfloat162 v = __floats2bfloat162_rn(x, y);
    unsigned u;
    memcpy(&u, &v, 4);
    return u;
}

static __device__ __forceinline__ unsigned short f2bf(float x) {
    __nv_bfloat16 v = __float2bfloat16(x);
    unsigned short u;
    memcpy(&u, &v, 2);
    return u;
}

static __device__ __forceinline__ float bf2f(unsigned short u) {
    __nv_bfloat16 v;
    memcpy(&v, &u, 2);
    return __bfloat162float(v);
}

static __device__ __forceinline__ void cp16(unsigned saddr, const void* gaddr) {
    asm volatile("cp.async.cg.shared.global [%0], [%1], 16;\n"
                 :: "r"(saddr), "l"(gaddr));
}
static __device__ __forceinline__ void cp_commit() {
    asm volatile("cp.async.commit_group;\n");
}
template <int N>
static __device__ __forceinline__ void cp_wait() {
    asm volatile("cp.async.wait_group %0;\n" :: "n"(N));
}

// ---- mbarrier + 1D bulk-copy helpers ----
static __device__ __forceinline__ void mbar_init(unsigned bar, unsigned count) {
    asm volatile("mbarrier.init.shared.b64 [%0], %1;" :: "r"(bar), "r"(count) : "memory");
}
static __device__ __forceinline__ void mbar_expect(unsigned bar, unsigned bytes) {
    asm volatile("mbarrier.arrive.expect_tx.shared.b64 _, [%0], %1;"
                 :: "r"(bar), "r"(bytes) : "memory");
}
static __device__ __forceinline__ void bulk_g2s(unsigned dst, const void* src,
                                                unsigned bytes, unsigned bar) {
    asm volatile("cp.async.bulk.shared::cta.global.mbarrier::complete_tx::bytes "
                 "[%0], [%1], %2, [%3];"
                 :: "r"(dst), "l"(src), "r"(bytes), "r"(bar) : "memory");
}
static __device__ __forceinline__ void mbar_wait(unsigned bar, unsigned parity) {
    asm volatile("{\n\t"
                 ".reg .pred p;\n\t"
                 "WAIT_%=:\n\t"
                 "mbarrier.try_wait.parity.shared::cta.b64 p, [%0], %1;\n\t"
                 "@!p bra WAIT_%=;\n\t"
                 "}"
                 :: "r"(bar), "r"(parity) : "memory");
}

// Init-time software barrier (atomic, self-resetting across replays).
static __device__ __forceinline__ void groupbar(int g) {
    __threadfence();
    __syncthreads();
    if (threadIdx.x == 0) {
        const int gi = g * 32;
        unsigned gen = g_ggen[gi];
        if (atomicAdd(&g_gcnt[gi], 1) == 15) {
            g_gcnt[gi] = 0;
            __threadfence();
            g_ggen[gi] = gen + 1;
        } else {
            while (g_ggen[gi] == gen) { }
            __threadfence();
        }
    }
    __syncthreads();
}

// ---------------------------------------------------------------------------
// Packing kernels (hi/lo split, pairing baked into column order)
// ---------------------------------------------------------------------------
__global__ void pack_a_kernel(const float* __restrict__ A,
                              unsigned short* __restrict__ Ap)
{
    const size_t idx  = (size_t)blockIdx.x * blockDim.x + threadIdx.x;
    const size_t base = idx * 4;
    const size_t m    = base >> 9;
    const int    k    = (int)(base & 511);
    const float4 v = *(const float4*)(A + base);

    unsigned short h0 = f2bf(v.x), h1 = f2bf(v.y), h2 = f2bf(v.z), h3 = f2bf(v.w);
    unsigned short l0 = f2bf(v.x - bf2f(h0));
    unsigned short l1 = f2bf(v.y - bf2f(h1));
    unsigned short l2 = f2bf(v.z - bf2f(h2));
    unsigned short l3 = f2bf(v.w - bf2f(h3));

    uint2 hv, lv;
    hv.x = (unsigned)h0 | ((unsigned)h1 << 16);
    hv.y = (unsigned)h2 | ((unsigned)h3 << 16);
    lv.x = (unsigned)l0 | ((unsigned)l1 << 16);
    lv.y = (unsigned)l2 | ((unsigned)l3 << 16);

    unsigned short* row = Ap + m * KP;
    *(uint2*)(row + k)        = hv;
    *(uint2*)(row + 512 + k)  = lv;
    *(uint2*)(row + 1024 + k) = hv;
}

__global__ void pack_w_kernel(const float* __restrict__ W,
                              unsigned short* __restrict__ Wp, int N)
{
    const int idx = blockIdx.x * blockDim.x + threadIdx.x;
    if (idx >= N * 512) return;
    const int n = idx / 512;
    const int k = idx % 512;
    const float v = W[(size_t)k * N + n];
    unsigned short hi = f2bf(v);
    unsigned short lo = f2bf(v - bf2f(hi));
    unsigned short* row = Wp + (size_t)n * KP;
    row[k]        = hi;
    row[512 + k]  = hi;
    row[1024 + k] = lo;
}

// ---------------------------------------------------------------------------
// bf16 tensor-core GEMM (proven round-8 version): 4-stage cp.async pipeline,
// BM=128, BN=128, BK=32, 256 threads, 8 warps (2m x 4n), warp tile 64x32.
// ---------------------------------------------------------------------------
#define TSTRIDE 40
#define GSTAGES 4
#define GST_HALVES (128 * TSTRIDE)
#define GST_BYTES  (GST_HALVES * 2)
#define GSMEM_TOTAL (GSTAGES * GST_BYTES * 2)

template <bool RELU, bool PACK>
__global__ __launch_bounds__(256, 2)
void bgemm_kernel(const unsigned short* __restrict__ Ap,
                  const unsigned short* __restrict__ Wp,
                  const float* __restrict__ bias,
                  float* __restrict__ Cf,
                  unsigned short* __restrict__ Cp,
                  int N)
{
    extern __shared__ char gsm[];
    unsigned short* As = (unsigned short*)gsm;
    unsigned short* Bs = (unsigned short*)(gsm + GSTAGES * GST_BYTES);

    const int tid  = threadIdx.x;
    const int m0   = blockIdx.y * 128;
    const int n0   = blockIdx.x * 128;
    const int wid  = tid >> 5;
    const int lane = tid & 31;
    const int wm   = wid & 1;
    const int wn   = wid >> 1;

    const int lrow = tid >> 1;
    const int lcol = (tid & 1) * 16;
    const unsigned short* Ag = Ap + (size_t)(m0 + lrow) * KP + lcol;
    const unsigned short* Bg = Wp + (size_t)(n0 + lrow) * KP + lcol;

    const unsigned uA0 = smem_u32(As);
    const unsigned uB0 = smem_u32(Bs);
    const unsigned sa0 = uA0 + (unsigned)(lrow * TSTRIDE + lcol) * 2;
    const unsigned sb0 = uB0 + (unsigned)(lrow * TSTRIDE + lcol) * 2;

    const int aj  = lane >> 3;
    const int ar  = (aj & 1) * 8 + (lane & 7);
    const int akq = (aj >> 1) * 8;

    float acc[4][4][4];
#pragma unroll
    for (int i = 0; i < 4; i++)
#pragma unroll
        for (int j = 0; j < 4; j++)
#pragma unroll
            for (int q = 0; q < 4; q++) acc[i][j][q] = 0.0f;

#define G_ISSUE(it_) do {                                              \
        const int _buf = (it_) & (GSTAGES - 1);                        \
        const int _k0  = (it_) * 32;                                   \
        cp16(sa0 + _buf * GST_BYTES,      Ag + _k0);                   \
        cp16(sa0 + _buf * GST_BYTES + 16, Ag + _k0 + 8);               \
        cp16(sb0 + _buf * GST_BYTES,      Bg + _k0);                   \
        cp16(sb0 + _buf * GST_BYTES + 16, Bg + _k0 + 8);               \
        cp_commit();                                                   \
    } while (0)

    G_ISSUE(0); G_ISSUE(1); G_ISSUE(2);

    const int NITER = KP / 32;   // 48
    for (int it = 0; it < NITER; it++) {
        if (it < NITER - 2)       cp_wait<2>();
        else if (it == NITER - 2) cp_wait<1>();
        else                      cp_wait<0>();
        __syncthreads();
        if (it + 3 < NITER) G_ISSUE(it + 3);

        const int buf = it & (GSTAGES - 1);
        const unsigned uA = uA0 + (unsigned)buf * GST_BYTES;
        const unsigned uB = uB0 + (unsigned)buf * GST_BYTES;

#pragma unroll
        for (int kk = 0; kk < 32; kk += 16) {
            unsigned a[4][4], b[2][4];
#pragma unroll
            for (int mi = 0; mi < 4; mi++)
                ldsm_x4(a[mi][0], a[mi][1], a[mi][2], a[mi][3],
                        uA + (unsigned)((wm * 64 + mi * 16 + ar) * TSTRIDE + kk + akq) * 2);
#pragma unroll
            for (int p = 0; p < 2; p++)
                ldsm_x4(b[p][0], b[p][1], b[p][2], b[p][3],
                        uB + (unsigned)((wn * 32 + p * 16 + ar) * TSTRIDE + kk + akq) * 2);
#pragma unroll
            for (int mi = 0; mi < 4; mi++) {
#pragma unroll
                for (int p = 0; p < 2; p++) {
                    mma_bf16(acc[mi][2*p][0], acc[mi][2*p][1], acc[mi][2*p][2], acc[mi][2*p][3],
                             a[mi][0], a[mi][1], a[mi][2], a[mi][3], b[p][0], b[p][2]);
                    mma_bf16(acc[mi][2*p+1][0], acc[mi][2*p+1][1], acc[mi][2*p+1][2], acc[mi][2*p+1][3],
                             a[mi][0], a[mi][1], a[mi][2], a[mi][3], b[p][1], b[p][3]);
                }
            }
        }
    }
#undef G_ISSUE

    const int quad = lane >> 2;
    const int tq   = lane & 3;
#pragma unroll
    for (int mi = 0; mi < 4; mi++) {
#pragma unroll
        for (int ni = 0; ni < 4; ni++) {
            const int n = n0 + wn * 32 + ni * 8 + tq * 2;
            const float bb0 = bias[n], bb1 = bias[n + 1];
#pragma unroll
            for (int half = 0; half < 2; half++) {
                const int m = m0 + wm * 64 + mi * 16 + quad + half * 8;
                float v0 = acc[mi][ni][half * 2 + 0] + bb0;
                float v1 = acc[mi][ni][half * 2 + 1] + bb1;
                if (RELU) { v0 = fmaxf(v0, 0.f); v1 = fmaxf(v1, 0.f); }
                if (PACK) {
                    unsigned short h0 = f2bf(v0), h1 = f2bf(v1);
                    unsigned short l0 = f2bf(v0 - bf2f(h0));
                    unsigned short l1 = f2bf(v1 - bf2f(h1));
                    unsigned hv = (unsigned)h0 | ((unsigned)h1 << 16);
                    unsigned lv = (unsigned)l0 | ((unsigned)l1 << 16);
                    unsigned short* row = Cp + (size_t)m * KP;
                    *(unsigned*)(row + n)        = hv;
                    *(unsigned*)(row + 512 + n)  = lv;
                    *(unsigned*)(row + 1024 + n) = hv;
                } else {
                    float2 v; v.x = v0; v.y = v1;
                    *(float2*)(Cf + (size_t)m * N + n) = v;
                }
            }
        }
    }
}

// ---------------------------------------------------------------------------
// Persistent recurrence kernel, warp-specialized comm version.
// Warps 0-7: MMA. Warp 8: h-chunk copies. Warp 9: h1-chunk copies (overlapped
// with phase A MMA). xh prefetched into registers at step top.
// ---------------------------------------------------------------------------
#define WS1_STRIDE 1032
#define WS2_STRIDE 520

#define OFF_WS1  0
#define OFF_WS2  (OFF_WS1 + 32 * WS1_STRIDE * 2)     // 66048
#define OFF_ACH  (OFF_WS2 + 64 * WS2_STRIDE * 2)     // 132608 (128B aligned)
#define OFF_H1S  (OFF_ACH + 65536)                   // 198144
#define OFF_B1   (OFF_H1S + 32768)                   // 230912
#define OFF_B2   (OFF_B1 + 32 * 4)                   // 231040
#define OFF_LEN  (OFF_B2 + 64 * 4)                   // 231296
#define OFF_MBAR (OFF_LEN + 32 * 4)                  // 231424
#define SMEM_TOTAL (OFF_MBAR + 4 * 8)                // 231456

__global__ __launch_bounds__(RTHR, 1)
void recurrence_tc(const float* __restrict__ W1h,
                   const float* __restrict__ b1h,
                   const float* __restrict__ W2h,
                   const float* __restrict__ b2h,
                   const int*   __restrict__ lens,
                   float* __restrict__ out)
{
    extern __shared__ char smem[];
    unsigned short* ws1 = (unsigned short*)(smem + OFF_WS1);
    unsigned short* ws2 = (unsigned short*)(smem + OFF_WS2);
    float* b1s = (float*)(smem + OFF_B1);
    float* b2s = (float*)(smem + OFF_B2);
    int*   lns = (int*)(smem + OFF_LEN);

    const unsigned u_ws1 = smem_u32(ws1);
    const unsigned u_ws2 = smem_u32(ws2);
    const unsigned u_ach = smem_u32(smem + OFF_ACH);
    const unsigned u_h1s = smem_u32(smem + OFF_H1S);
    const unsigned u_bar = smem_u32(smem + OFF_MBAR);   // barA, barB

    const int tid  = threadIdx.x;
    const int cta  = blockIdx.x;
    const int wid  = tid >> 5;       // 0..9
    const int lane = tid & 31;
    const int quad = lane >> 2;
    const int tq   = lane & 3;

    const int grp = cta >> 4;
    const int mem = cta & 15;
    const int rA = grp * 32;
    const int cA = mem * 32;
    const int cB = mem * 64;

    const int mh = wid & 1;
    const int nb = wid >> 1;
    const int np = wid >> 1;

    for (int i = tid; i < 1024 * 32; i += RTHR) {
        int k = i >> 5, n = i & 31;
        ws1[n * WS1_STRIDE + k] = f2bf(W1h[(size_t)k * HALF_H + cA + n]);
    }
    for (int i = tid; i < 512 * 64; i += RTHR) {
        int k = i >> 6, n = i & 63;
        ws2[n * WS2_STRIDE + k] = f2bf(W2h[(size_t)k * HIDDEN + cB + n]);
    }
    if (tid < 32) { b1s[tid] = b1h[cA + tid]; lns[tid] = lens[rA + tid]; }
    if (tid < 64) b2s[tid] = b2h[cB + tid];

    if (tid == 0) {
        mbar_init(u_bar + 0, 16);    // barA (h chunks)
        mbar_init(u_bar + 8, 16);    // barB (h1 chunks)
        g_hflag[grp][mem * 32]  = 0; // reset own flags (replay-safe)
        g_h1flag[grp][mem * 32] = 0;
    }

    // zero own h chunk (zeros are swizzle-invariant)
    {
        unsigned* hz = (unsigned*)g_h_bf16 + (size_t)(grp * 16 + mem) * 1024;
        for (int i = tid; i < 1024; i += RTHR) hz[i] = 0u;
    }

    groupbar(grp);   // flags reset + zeros + mbar inits visible group-wide

    // chunk bases in global (bytes)
    const char* ghg  = (const char*)g_h_bf16  + (size_t)grp * 16 * 4096;
    const char* gh1g = (const char*)g_h1_bf16 + (size_t)grp * 16 * 2048;

    // =============== COMM WARPS ===============
    if (wid == 8) {
        // h-chunk copier
        for (int t = 0; t < SEQLEN; t++) {
            if (lane < 16) {
                while (g_hflag[grp][lane * 32] < (unsigned)t) { }
                mbar_expect(u_bar + 0, 4096);
                bulk_g2s(u_ach + (unsigned)lane * 4096, ghg + (size_t)lane * 4096,
                         4096, u_bar + 0);
            }
            __syncthreads();
        }
        return;
    }
    if (wid == 9) {
        // h1-chunk copier (overlaps phase A MMA)
        for (int t = 0; t < SEQLEN; t++) {
            if (lane < 16) {
                while (g_h1flag[grp][lane * 32] < (unsigned)(t + 1)) { }
                mbar_expect(u_bar + 8, 2048);
                bulk_g2s(u_h1s + (unsigned)lane * 2048, gh1g + (size_t)lane * 2048,
                         2048, u_bar + 8);
            }
            __syncthreads();
        }
        return;
    }

    // =============== MMA WARPS (0..7) ===============
    float hreg[2][4];
#pragma unroll
    for (int b = 0; b < 2; b++)
#pragma unroll
        for (int j = 0; j < 4; j++) hreg[b][j] = 0.0f;

    // ldmatrix lane mapping
    const int aj   = lane >> 3;
    const int arow = mh * 16 + (aj & 1) * 8 + (lane & 7);   // 0..31
    const int ku   = aj >> 1;                               // 0/1
    const int swzA = arow & 7;
    const int swzB = arow & 3;
    const int li   = lane & 15;
    const int brow_in = li & 7;
    const int bkq  = (li >> 3) * 8;

    for (int t = 0; t < SEQLEN; t++) {
        const unsigned par = (unsigned)(t & 1);

        // xh register prefetch (independent of all flags; consumed in phase B)
        float2 xhp[2][2];
#pragma unroll
        for (int b = 0; b < 2; b++) {
#pragma unroll
            for (int half = 0; half < 2; half++) {
                const int n = np * 16 + b * 8 + tq * 2;
                const int m = mh * 16 + quad + half * 8;
                const size_t oidx = ((size_t)(rA + m) * SEQLEN + t) * HIDDEN + cB + n;
                xhp[b][half] = __ldg((const float2*)(out + oidx));
            }
        }

        // ============ PHASE A: h1 = relu(h @ W1h + b1) ============
        mbar_wait(u_bar + 0, par);

        float ca[4] = {0.f, 0.f, 0.f, 0.f};
#pragma unroll 8
        for (int kk = 0; kk < 1024; kk += 16) {
            const int c  = kk >> 6;
            const int lu = ((kk & 63) >> 3) + ku;
            unsigned a0, a1, a2, a3, b0, b1;
            ldsm_x4(a0, a1, a2, a3,
                    u_ach + (unsigned)(c * 4096 + arow * 128 + ((lu ^ swzA) << 4)));
            ldsm_x2(b0, b1, u_ws1 + (unsigned)((nb * 8 + brow_in) * WS1_STRIDE + kk + bkq) * 2);
            mma_bf16(ca[0], ca[1], ca[2], ca[3], a0, a1, a2, a3, b0, b1);
        }
        {
            // write own h1 chunk: [32 rows][32 cols], unit u = nb, swizzle u^(r&3)
            const int n = nb * 8 + tq * 2;
            const int m0w = mh * 16 + quad;
            float v0 = fmaxf(ca[0] + b1s[n], 0.f);
            float v1 = fmaxf(ca[1] + b1s[n + 1], 0.f);
            float v2 = fmaxf(ca[2] + b1s[n], 0.f);
            float v3 = fmaxf(ca[3] + b1s[n + 1], 0.f);
            unsigned short* chunk = g_h1_bf16 + (size_t)(grp * 16 + mem) * 1024;
            const int r0 = m0w, r1 = m0w + 8;
            *(unsigned*)(chunk + r0 * 32 + ((nb ^ (r0 & 3)) << 3) + tq * 2) = pack_bf16(v0, v1);
            *(unsigned*)(chunk + r1 * 32 + ((nb ^ (r1 & 3)) << 3) + tq * 2) = pack_bf16(v2, v3);
        }
        __threadfence();
        asm volatile("bar.sync 1, 256;" ::: "memory");   // MMA warps only
        if (tid == 0) g_h1flag[grp][mem * 32] = (unsigned)(t + 1);

        // ============ PHASE B: h = tanh(xh + h1 @ W2h + b2) ============
        mbar_wait(u_bar + 8, par);

        float cb[2][4];
#pragma unroll
        for (int b = 0; b < 2; b++)
#pragma unroll
            for (int j = 0; j < 4; j++) cb[b][j] = 0.f;

#pragma unroll 8
        for (int kk = 0; kk < 512; kk += 16) {
            const int c  = kk >> 5;
            const int lu = ((kk & 31) >> 3) + ku;
            unsigned a0, a1, a2, a3;
            ldsm_x4(a0, a1, a2, a3,
                    u_h1s + (unsigned)(c * 2048 + arow * 64 + ((lu ^ swzB) << 4)));
#pragma unroll
            for (int b = 0; b < 2; b++) {
                unsigned b0, b1;
                ldsm_x2(b0, b1, u_ws2 + (unsigned)((np * 16 + b * 8 + brow_in) * WS2_STRIDE + kk + bkq) * 2);
                mma_bf16(cb[b][0], cb[b][1], cb[b][2], cb[b][3], a0, a1, a2, a3, b0, b1);
            }
        }

#pragma unroll
        for (int b = 0; b < 2; b++) {
            const int n = np * 16 + b * 8 + tq * 2;     // local col in 64
            const int u = np * 2 + b;                   // 16B unit 0..7
            const float bb0 = b2s[n], bb1 = b2s[n + 1];
#pragma unroll
            for (int half = 0; half < 2; half++) {
                const int m = mh * 16 + quad + half * 8;
                const int bat = rA + m;
                const int col = cB + n;
                const size_t oidx = ((size_t)bat * SEQLEN + t) * HIDDEN + col;
                const float2 xh = xhp[b][half];
                float nv0 = tanhf(xh.x + cb[b][half * 2 + 0] + bb0);
                float nv1 = tanhf(xh.y + cb[b][half * 2 + 1] + bb1);
                bool ok = t < lns[m];
                float h0 = ok ? nv0 : hreg[b][half * 2 + 0];
                float h1 = ok ? nv1 : hreg[b][half * 2 + 1];
                hreg[b][half * 2 + 0] = h0;
                hreg[b][half * 2 + 1] = h1;
                float2 hv; hv.x = h0; hv.y = h1;
                *(float2*)(out + oidx) = hv;
                // own h chunk: [32 rows][64 cols], unit u, swizzle u^(r&7)
                unsigned short* chunk = g_h_bf16 + (size_t)(grp * 16 + mem) * 2048;
                *(unsigned*)(chunk + m * 64 + ((u ^ (m & 7)) << 3) + tq * 2) = pack_bf16(h0, h1);
            }
        }
        __threadfence();
        __syncthreads();     // all 10 warps: WAR guard for ach/h1s reuse
        if (tid == 0) g_hflag[grp][mem * 32] = (unsigned)(t + 1);
    }
}

// ---------------------------------------------------------------------------
extern "C" void kernel_launch(void* const* d_in, const int* in_sizes, int n_in,
                              void* d_out, int out_size)
{
    const float* seq  = (const float*)d_in[0];
    const int*   lens = (const int*)  d_in[1];
    const float* w1x  = (const float*)d_in[2];
    const float* b1x  = (const float*)d_in[3];
    const float* w2x  = (const float*)d_in[4];
    const float* b2x  = (const float*)d_in[5];
    const float* w1h  = (const float*)d_in[6];
    const float* b1h  = (const float*)d_in[7];
    const float* w2h  = (const float*)d_in[8];
    const float* b2h  = (const float*)d_in[9];
    float* out = (float*)d_out;

    unsigned short *a1p, *hidp, *w1xp, *w2xp;
    cudaGetSymbolAddress((void**)&a1p,  g_a1p);
    cudaGetSymbolAddress((void**)&hidp, g_hidp);
    cudaGetSymbolAddress((void**)&w1xp, g_w1xp);
    cudaGetSymbolAddress((void**)&w2xp, g_w2xp);

    static bool attr_set = false;
    if (!attr_set) {
        cudaFuncSetAttribute(recurrence_tc,
                             cudaFuncAttributeMaxDynamicSharedMemorySize, SMEM_TOTAL);
        cudaFuncSetAttribute(bgemm_kernel<true, true>,
                             cudaFuncAttributeMaxDynamicSharedMemorySize, GSMEM_TOTAL);
        cudaFuncSetAttribute(bgemm_kernel<false, false>,
                             cudaFuncAttributeMaxDynamicSharedMemorySize, GSMEM_TOTAL);
        attr_set = true;
    }

    // Pack operands (hi/lo split)
    pack_a_kernel<<<(NTOK * EMB / 4) / 256, 256>>>(seq, a1p);
    pack_w_kernel<<<(HALF_H * 512 + 255) / 256, 256>>>(w1x, w1xp, HALF_H);
    pack_w_kernel<<<(HIDDEN * 512 + 255) / 256, 256>>>(w2x, w2xp, HIDDEN);

    // K1: hidp = pack(relu(seq @ w1x + b1x))
    bgemm_kernel<true, true><<<dim3(HALF_H / 128, NTOK / 128), 256, GSMEM_TOTAL>>>(
        a1p, w1xp, b1x, nullptr, hidp, HALF_H);

    // K2: out = hid @ w2x + b2x   (xh)
    bgemm_kernel<false, false><<<dim3(HIDDEN / 128, NTOK / 128), 256, GSMEM_TOTAL>>>(
        hidp, w2xp, b2x, out, nullptr, HIDDEN);

    // K3: persistent recurrence, warp-specialized comm
    recurrence_tc<<<NCTA, RTHR, SMEM_TOTAL>>>(w1h, b1h, w2h, b2h, lens, out);
}

// round 14
// speedup vs baseline: 1.1510x; 1.1510x over previous
#include <cuda_runtime.h>
#include <cuda_bf16.h>
#include <math.h>
#include <string.h>

// Problem constants (fixed by the dataset)
#define EMB     512
#define HIDDEN  1024
#define HALF_H  512
#define BATCH   256
#define SEQLEN  512
#define NTOK    (BATCH * SEQLEN)   // 131072
#define KP      1536               // 3 * 512 packed-K for split-bf16 GEMMs

#define NCTA    128
#define NTHR    256

// ---------------------------------------------------------------------------
// Device globals (allocation-free scratch)
// h / h1 exchange buffers are chunk-contiguous per producer CTA:
//   g_h_bf16 : [8 groups][16 producers][32 rows][64 cols]  (rows XOR-swizzled)
//   g_h1_bf16: [8 groups][16 producers][32 rows][32 cols]  (rows XOR-swizzled)
// ---------------------------------------------------------------------------
__device__ unsigned short g_a1p[(size_t)NTOK * KP];    // packed seq   [M][1536]
__device__ unsigned short g_hidp[(size_t)NTOK * KP];   // packed hid1  [M][1536]
__device__ unsigned short g_w1xp[HALF_H * KP];         // packed w1x   [512][1536] (n-major)
__device__ unsigned short g_w2xp[HIDDEN * KP];         // packed w2x   [1024][1536] (n-major)
__device__ unsigned short g_h_bf16[BATCH * HIDDEN];
__device__ unsigned short g_h1_bf16[BATCH * HALF_H];
__device__ volatile unsigned g_ggen[8 * 32];           // init barrier gen
__device__ unsigned g_gcnt[8 * 32];                    // init barrier count
__device__ volatile unsigned g_hflag[8][16 * 32];      // h ready flags (128B apart)
__device__ volatile unsigned g_h1flag[8][16 * 32];     // h1 ready flags

// ---------------------------------------------------------------------------
// Helpers
// ---------------------------------------------------------------------------
static __device__ __forceinline__ unsigned smem_u32(const void* p) {
    unsigned a;
    asm("{ .reg .u64 t; cvta.to.shared.u64 t, %1; cvt.u32.u64 %0, t; }"
        : "=r"(a) : "l"(p));
    return a;
}

static __device__ __forceinline__ void ldsm_x4(unsigned& r0, unsigned& r1,
                                               unsigned& r2, unsigned& r3,
                                               unsigned addr) {
    asm volatile("ldmatrix.sync.aligned.m8n8.x4.shared.b16 {%0,%1,%2,%3}, [%4];"
                 : "=r"(r0), "=r"(r1), "=r"(r2), "=r"(r3) : "r"(addr));
}

static __device__ __forceinline__ void ldsm_x2(unsigned& r0, unsigned& r1,
                                               unsigned addr) {
    asm volatile("ldmatrix.sync.aligned.m8n8.x2.shared.b16 {%0,%1}, [%2];"
                 : "=r"(r0), "=r"(r1) : "r"(addr));
}

static __device__ __forceinline__ void mma_bf16(float& c0, float& c1, float& c2, float& c3,
                                                unsigned a0, unsigned a1, unsigned a2, unsigned a3,
                                                unsigned b0, unsigned b1) {
    asm volatile("mma.sync.aligned.m16n8k16.row.col.f32.bf16.bf16.f32 "
                 "{%0,%1,%2,%3}, {%4,%5,%6,%7}, {%8,%9}, {%0,%1,%2,%3};"
                 : "+f"(c0), "+f"(c1), "+f"(c2), "+f"(c3)
                 : "r"(a0), "r"(a1), "r"(a2), "r"(a3), "r"(b0), "r"(b1));
}

static __device__ __forceinline__ unsigned pack_bf16(float x, float y) {
    __nv_bfloat162 v = __floats2bfloat162_rn(x, y);
    unsigned u;
    memcpy(&u, &v, 4);
    return u;
}

static __device__ __forceinline__ unsigned short f2bf(float x) {
    __nv_bfloat16 v = __float2bfloat16(x);
    unsigned short u;
    memcpy(&u, &v, 2);
    return u;
}

static __device__ __forceinline__ float bf2f(unsigned short u) {
    __nv_bfloat16 v;
    memcpy(&v, &u, 2);
    return __bfloat162float(v);
}

static __device__ __forceinline__ void cp16(unsigned saddr, const void* gaddr) {
    asm volatile("cp.async.cg.shared.global [%0], [%1], 16;\n"
                 :: "r"(saddr), "l"(gaddr));
}
static __device__ __forceinline__ void cp_commit() {
    asm volatile("cp.async.commit_group;\n");
}
template <int N>
static __device__ __forceinline__ void cp_wait() {
    asm volatile("cp.async.wait_group %0;\n" :: "n"(N));
}

// ---- mbarrier + 1D bulk-copy helpers ----
static __device__ __forceinline__ void mbar_init(unsigned bar, unsigned count) {
    asm volatile("mbarrier.init.shared.b64 [%0], %1;" :: "r"(bar), "r"(count) : "memory");
}
static __device__ __forceinline__ void mbar_expect(unsigned bar, unsigned bytes) {
    asm volatile("mbarrier.arrive.expect_tx.shared.b64 _, [%0], %1;"
                 :: "r"(bar), "r"(bytes) : "memory");
}
static __device__ __forceinline__ void bulk_g2s(unsigned dst, const void* src,
                                                unsigned bytes, unsigned bar) {
    asm volatile("cp.async.bulk.shared::cta.global.mbarrier::complete_tx::bytes "
                 "[%0], [%1], %2, [%3];"
                 :: "r"(dst), "l"(src), "r"(bytes), "r"(bar) : "memory");
}
static __device__ __forceinline__ void mbar_wait(unsigned bar, unsigned parity) {
    asm volatile("{\n\t"
                 ".reg .pred p;\n\t"
                 "WAIT_%=:\n\t"
                 "mbarrier.try_wait.parity.shared::cta.b64 p, [%0], %1;\n\t"
                 "@!p bra WAIT_%=;\n\t"
                 "}"
                 :: "r"(bar), "r"(parity) : "memory");
}

// Init-time software barrier (atomic, self-resetting across replays).
static __device__ __forceinline__ void groupbar(int g) {
    __threadfence();
    __syncthreads();
    if (threadIdx.x == 0) {
        const int gi = g * 32;
        unsigned gen = g_ggen[gi];
        if (atomicAdd(&g_gcnt[gi], 1) == 15) {
            g_gcnt[gi] = 0;
            __threadfence();
            g_ggen[gi] = gen + 1;
        } else {
            while (g_ggen[gi] == gen) { }
            __threadfence();
        }
    }
    __syncthreads();
}

// ---------------------------------------------------------------------------
// Packing kernels (hi/lo split, pairing baked into column order)
// ---------------------------------------------------------------------------
__global__ void pack_a_kernel(const float* __restrict__ A,
                              unsigned short* __restrict__ Ap)
{
    const size_t idx  = (size_t)blockIdx.x * blockDim.x + threadIdx.x;
    const size_t base = idx * 4;
    const size_t m    = base >> 9;
    const int    k    = (int)(base & 511);
    const float4 v = *(const float4*)(A + base);

    unsigned short h0 = f2bf(v.x), h1 = f2bf(v.y), h2 = f2bf(v.z), h3 = f2bf(v.w);
    unsigned short l0 = f2bf(v.x - bf2f(h0));
    unsigned short l1 = f2bf(v.y - bf2f(h1));
    unsigned short l2 = f2bf(v.z - bf2f(h2));
    unsigned short l3 = f2bf(v.w - bf2f(h3));

    uint2 hv, lv;
    hv.x = (unsigned)h0 | ((unsigned)h1 << 16);
    hv.y = (unsigned)h2 | ((unsigned)h3 << 16);
    lv.x = (unsigned)l0 | ((unsigned)l1 << 16);
    lv.y = (unsigned)l2 | ((unsigned)l3 << 16);

    unsigned short* row = Ap + m * KP;
    *(uint2*)(row + k)        = hv;
    *(uint2*)(row + 512 + k)  = lv;
    *(uint2*)(row + 1024 + k) = hv;
}

__global__ void pack_w_kernel(const float* __restrict__ W,
                              unsigned short* __restrict__ Wp, int N)
{
    const int idx = blockIdx.x * blockDim.x + threadIdx.x;
    if (idx >= N * 512) return;
    const int n = idx / 512;
    const int k = idx % 512;
    const float v = W[(size_t)k * N + n];
    unsigned short hi = f2bf(v);
    unsigned short lo = f2bf(v - bf2f(hi));
    unsigned short* row = Wp + (size_t)n * KP;
    row[k]        = hi;
    row[512 + k]  = hi;
    row[1024 + k] = lo;
}

// ---------------------------------------------------------------------------
// bf16 tensor-core GEMM (round-8 proven core) + length-based tile skip.
// Each m-tile lies in one batch row (S=512, BM=128): skip the CTA entirely
// when its first token index >= len[b] (outputs never consumed downstream).
// BM=128, BN=128, BK=32, 256 threads, 8 warps (2m x 4n), warp tile 64x32.
// ---------------------------------------------------------------------------
#define TSTRIDE 40
#define GSTAGES 4
#define GST_HALVES (128 * TSTRIDE)
#define GST_BYTES  (GST_HALVES * 2)
#define GSMEM_TOTAL (GSTAGES * GST_BYTES * 2)

template <bool RELU, bool PACK>
__global__ __launch_bounds__(256, 2)
void bgemm_kernel(const unsigned short* __restrict__ Ap,
                  const unsigned short* __restrict__ Wp,
                  const float* __restrict__ bias,
                  float* __restrict__ Cf,
                  unsigned short* __restrict__ Cp,
                  int N,
                  const int* __restrict__ lens)
{
    extern __shared__ char gsm[];
    unsigned short* As = (unsigned short*)gsm;
    unsigned short* Bs = (unsigned short*)(gsm + GSTAGES * GST_BYTES);

    const int m0 = blockIdx.y * 128;

    // length-based tile skip: tokens [s0, s0+128) of batch row b dead if
    // s0 >= len[b] (xh/hid for t >= len are never consumed).
    {
        const int b  = m0 >> 9;          // batch row (S = 512)
        const int s0 = m0 & 511;         // first token index in row
        if (s0 >= __ldg(&lens[b])) return;
    }

    const int tid  = threadIdx.x;
    const int n0   = blockIdx.x * 128;
    const int wid  = tid >> 5;
    const int lane = tid & 31;
    const int wm   = wid & 1;
    const int wn   = wid >> 1;

    const int lrow = tid >> 1;
    const int lcol = (tid & 1) * 16;
    const unsigned short* Ag = Ap + (size_t)(m0 + lrow) * KP + lcol;
    const unsigned short* Bg = Wp + (size_t)(n0 + lrow) * KP + lcol;

    const unsigned uA0 = smem_u32(As);
    const unsigned uB0 = smem_u32(Bs);
    const unsigned sa0 = uA0 + (unsigned)(lrow * TSTRIDE + lcol) * 2;
    const unsigned sb0 = uB0 + (unsigned)(lrow * TSTRIDE + lcol) * 2;

    const int aj  = lane >> 3;
    const int ar  = (aj & 1) * 8 + (lane & 7);
    const int akq = (aj >> 1) * 8;

    float acc[4][4][4];
#pragma unroll
    for (int i = 0; i < 4; i++)
#pragma unroll
        for (int j = 0; j < 4; j++)
#pragma unroll
            for (int q = 0; q < 4; q++) acc[i][j][q] = 0.0f;

#define G_ISSUE(it_) do {                                              \
        const int _buf = (it_) & (GSTAGES - 1);                        \
        const int _k0  = (it_) * 32;                                   \
        cp16(sa0 + _buf * GST_BYTES,      Ag + _k0);                   \
        cp16(sa0 + _buf * GST_BYTES + 16, Ag + _k0 + 8);               \
        cp16(sb0 + _buf * GST_BYTES,      Bg + _k0);                   \
        cp16(sb0 + _buf * GST_BYTES + 16, Bg + _k0 + 8);               \
        cp_commit();                                                   \
    } while (0)

    G_ISSUE(0); G_ISSUE(1); G_ISSUE(2);

    const int NITER = KP / 32;   // 48
    for (int it = 0; it < NITER; it++) {
        if (it < NITER - 2)       cp_wait<2>();
        else if (it == NITER - 2) cp_wait<1>();
        else                      cp_wait<0>();
        __syncthreads();
        if (it + 3 < NITER) G_ISSUE(it + 3);

        const int buf = it & (GSTAGES - 1);
        const unsigned uA = uA0 + (unsigned)buf * GST_BYTES;
        const unsigned uB = uB0 + (unsigned)buf * GST_BYTES;

#pragma unroll
        for (int kk = 0; kk < 32; kk += 16) {
            unsigned a[4][4], b[2][4];
#pragma unroll
            for (int mi = 0; mi < 4; mi++)
                ldsm_x4(a[mi][0], a[mi][1], a[mi][2], a[mi][3],
                        uA + (unsigned)((wm * 64 + mi * 16 + ar) * TSTRIDE + kk + akq) * 2);
#pragma unroll
            for (int p = 0; p < 2; p++)
                ldsm_x4(b[p][0], b[p][1], b[p][2], b[p][3],
                        uB + (unsigned)((wn * 32 + p * 16 + ar) * TSTRIDE + kk + akq) * 2);
#pragma unroll
            for (int mi = 0; mi < 4; mi++) {
#pragma unroll
                for (int p = 0; p < 2; p++) {
                    mma_bf16(acc[mi][2*p][0], acc[mi][2*p][1], acc[mi][2*p][2], acc[mi][2*p][3],
                             a[mi][0], a[mi][1], a[mi][2], a[mi][3], b[p][0], b[p][2]);
                    mma_bf16(acc[mi][2*p+1][0], acc[mi][2*p+1][1], acc[mi][2*p+1][2], acc[mi][2*p+1][3],
                             a[mi][0], a[mi][1], a[mi][2], a[mi][3], b[p][1], b[p][3]);
                }
            }
        }
    }
#undef G_ISSUE

    const int quad = lane >> 2;
    const int tq   = lane & 3;
#pragma unroll
    for (int mi = 0; mi < 4; mi++) {
#pragma unroll
        for (int ni = 0; ni < 4; ni++) {
            const int n = n0 + wn * 32 + ni * 8 + tq * 2;
            const float bb0 = bias[n], bb1 = bias[n + 1];
#pragma unroll
            for (int half = 0; half < 2; half++) {
                const int m = m0 + wm * 64 + mi * 16 + quad + half * 8;
                float v0 = acc[mi][ni][half * 2 + 0] + bb0;
                float v1 = acc[mi][ni][half * 2 + 1] + bb1;
                if (RELU) { v0 = fmaxf(v0, 0.f); v1 = fmaxf(v1, 0.f); }
                if (PACK) {
                    unsigned short h0 = f2bf(v0), h1 = f2bf(v1);
                    unsigned short l0 = f2bf(v0 - bf2f(h0));
                    unsigned short l1 = f2bf(v1 - bf2f(h1));
                    unsigned hv = (unsigned)h0 | ((unsigned)h1 << 16);
                    unsigned lv = (unsigned)l0 | ((unsigned)l1 << 16);
                    unsigned short* row = Cp + (size_t)m * KP;
                    *(unsigned*)(row + n)        = hv;
                    *(unsigned*)(row + 512 + n)  = lv;
                    *(unsigned*)(row + 1024 + n) = hv;
                } else {
                    float2 v; v.x = v0; v.y = v1;
                    *(float2*)(Cf + (size_t)m * N + n) = v;
                }
            }
        }
    }
}

// ---------------------------------------------------------------------------
// Persistent recurrence kernel (round-10 best): barrier-free dataflow.
// Per phase: producers set per-CTA flags after writing their chunk; consumer
// threads 0..15 poll flag j and bulk-copy chunk j (aggregate mbar, count 16).
// ---------------------------------------------------------------------------
#define WS1_STRIDE 1032
#define WS2_STRIDE 520

#define OFF_WS1  0
#define OFF_WS2  (OFF_WS1 + 32 * WS1_STRIDE * 2)     // 66048
#define OFF_ACH  (OFF_WS2 + 64 * WS2_STRIDE * 2)     // 132608 (128B aligned)
#define OFF_H1S  (OFF_ACH + 65536)                   // 198144
#define OFF_B1   (OFF_H1S + 32768)                   // 230912
#define OFF_B2   (OFF_B1 + 32 * 4)                   // 231040
#define OFF_LEN  (OFF_B2 + 64 * 4)                   // 231296
#define OFF_MBAR (OFF_LEN + 32 * 4)                  // 231424
#define SMEM_TOTAL (OFF_MBAR + 4 * 8)                // 231456

__global__ __launch_bounds__(NTHR, 1)
void recurrence_tc(const float* __restrict__ W1h,
                   const float* __restrict__ b1h,
                   const float* __restrict__ W2h,
                   const float* __restrict__ b2h,
                   const int*   __restrict__ lens,
                   float* __restrict__ out)
{
    extern __shared__ char smem[];
    unsigned short* ws1 = (unsigned short*)(smem + OFF_WS1);
    unsigned short* ws2 = (unsigned short*)(smem + OFF_WS2);
    float* b1s = (float*)(smem + OFF_B1);
    float* b2s = (float*)(smem + OFF_B2);
    int*   lns = (int*)(smem + OFF_LEN);
    const float* xs = (const float*)(smem + OFF_ACH);   // xh staging (phase B)

    const unsigned u_ws1 = smem_u32(ws1);
    const unsigned u_ws2 = smem_u32(ws2);
    const unsigned u_ach = smem_u32(smem + OFF_ACH);
    const unsigned u_h1s = smem_u32(smem + OFF_H1S);
    const unsigned u_bar = smem_u32(smem + OFF_MBAR);   // barA, barB

    const int tid  = threadIdx.x;
    const int cta  = blockIdx.x;
    const int wid  = tid >> 5;
    const int lane = tid & 31;
    const int quad = lane >> 2;
    const int tq   = lane & 3;

    const int grp = cta >> 4;
    const int mem = cta & 15;
    const int rA = grp * 32;
    const int cA = mem * 32;
    const int cB = mem * 64;

    const int mh = wid & 1;
    const int nb = wid >> 1;
    const int np = wid >> 1;

    for (int i = tid; i < 1024 * 32; i += NTHR) {
        int k = i >> 5, n = i & 31;
        ws1[n * WS1_STRIDE + k] = f2bf(W1h[(size_t)k * HALF_H + cA + n]);
    }
    for (int i = tid; i < 512 * 64; i += NTHR) {
        int k = i >> 6, n = i & 63;
        ws2[n * WS2_STRIDE + k] = f2bf(W2h[(size_t)k * HIDDEN + cB + n]);
    }
    if (tid < 32) { b1s[tid] = b1h[cA + tid]; lns[tid] = lens[rA + tid]; }
    if (tid < 64) b2s[tid] = b2h[cB + tid];

    if (tid == 0) {
        mbar_init(u_bar + 0, 16);    // barA
        mbar_init(u_bar + 8, 16);    // barB
        g_hflag[grp][mem * 32]  = 0; // reset own flags (replay-safe)
        g_h1flag[grp][mem * 32] = 0;
    }

    // zero own h chunk (zeros are swizzle-invariant)
    {
        unsigned* hz = (unsigned*)g_h_bf16 + (size_t)(grp * 16 + mem) * 1024;
        for (int i = tid; i < 1024; i += NTHR) hz[i] = 0u;
    }

    float hreg[2][4];
#pragma unroll
    for (int b = 0; b < 2; b++)
#pragma unroll
        for (int j = 0; j < 4; j++) hreg[b][j] = 0.0f;

    groupbar(grp);   // flags reset + zeros + mbar inits visible group-wide

    // ldmatrix lane mapping
    const int aj   = lane >> 3;
    const int arow = mh * 16 + (aj & 1) * 8 + (lane & 7);   // 0..31
    const int ku   = aj >> 1;                               // 0/1
    const int swzA = arow & 7;
    const int swzB = arow & 3;
    const int li   = lane & 15;
    const int brow_in = li & 7;
    const int bkq  = (li >> 3) * 8;

    // chunk bases in global (bytes)
    const char* ghg  = (const char*)g_h_bf16  + (size_t)grp * 16 * 4096;
    const char* gh1g = (const char*)g_h1_bf16 + (size_t)grp * 16 * 2048;

    for (int t = 0; t < SEQLEN; t++) {
        const unsigned par = (unsigned)(t & 1);

        // ============ PHASE A: h1 = relu(h @ W1h + b1) ============
        if (tid < 16) {
            while (g_hflag[grp][tid * 32] < (unsigned)t) { }
            mbar_expect(u_bar + 0, 4096);
            bulk_g2s(u_ach + (unsigned)tid * 4096, ghg + (size_t)tid * 4096,
                     4096, u_bar + 0);
        }
        mbar_wait(u_bar + 0, par);

        float ca[4] = {0.f, 0.f, 0.f, 0.f};
#pragma unroll 8
        for (int kk = 0; kk < 1024; kk += 16) {
            const int c  = kk >> 6;
            const int lu = ((kk & 63) >> 3) + ku;
            unsigned a0, a1, a2, a3, b0, b1;
            ldsm_x4(a0, a1, a2, a3,
                    u_ach + (unsigned)(c * 4096 + arow * 128 + ((lu ^ swzA) << 4)));
            ldsm_x2(b0, b1, u_ws1 + (unsigned)((nb * 8 + brow_in) * WS1_STRIDE + kk + bkq) * 2);
            mma_bf16(ca[0], ca[1], ca[2], ca[3], a0, a1, a2, a3, b0, b1);
        }
        {
            // write own h1 chunk: [32 rows][32 cols], unit u = nb, swizzle u^(r&3)
            const int n = nb * 8 + tq * 2;
            const int m0w = mh * 16 + quad;
            float v0 = fmaxf(ca[0] + b1s[n], 0.f);
            float v1 = fmaxf(ca[1] + b1s[n + 1], 0.f);
            float v2 = fmaxf(ca[2] + b1s[n], 0.f);
            float v3 = fmaxf(ca[3] + b1s[n + 1], 0.f);
            unsigned short* chunk = g_h1_bf16 + (size_t)(grp * 16 + mem) * 1024;
            const int r0 = m0w, r1 = m0w + 8;
            *(unsigned*)(chunk + r0 * 32 + ((nb ^ (r0 & 3)) << 3) + tq * 2) = pack_bf16(v0, v1);
            *(unsigned*)(chunk + r1 * 32 + ((nb ^ (r1 & 3)) << 3) + tq * 2) = pack_bf16(v2, v3);
        }
        __threadfence();
        __syncthreads();
        if (tid == 0) g_h1flag[grp][mem * 32] = (unsigned)(t + 1);

        // ============ PHASE B: h = tanh(xh + h1 @ W2h + b2) ============
        if (tid < 16) {
            while (g_h1flag[grp][tid * 32] < (unsigned)(t + 1)) { }
            mbar_expect(u_bar + 8, 2048);
            bulk_g2s(u_h1s + (unsigned)tid * 2048, gh1g + (size_t)tid * 2048,
                     2048, u_bar + 8);
        }
        // xh prefetch into (now idle) ach region: 32 rows x 64 cols f32 = 8KB
#pragma unroll
        for (int j = 0; j < 2; j++) {
            const int lin = tid * 2 + j;
            const int row = lin >> 4;
            const int u   = lin & 15;
            cp16(u_ach + (unsigned)lin * 16,
                 out + ((size_t)(rA + row) * SEQLEN + t) * HIDDEN + cB + u * 4);
        }
        cp_commit();

        mbar_wait(u_bar + 8, par);

        float cb[2][4];
#pragma unroll
        for (int b = 0; b < 2; b++)
#pragma unroll
            for (int j = 0; j < 4; j++) cb[b][j] = 0.f;

#pragma unroll 8
        for (int kk = 0; kk < 512; kk += 16) {
            const int c  = kk >> 5;
            const int lu = ((kk & 31) >> 3) + ku;
            unsigned a0, a1, a2, a3;
            ldsm_x4(a0, a1, a2, a3,
                    u_h1s + (unsigned)(c * 2048 + arow * 64 + ((lu ^ swzB) << 4)));
#pragma unroll
            for (int b = 0; b < 2; b++) {
                unsigned b0, b1;
                ldsm_x2(b0, b1, u_ws2 + (unsigned)((np * 16 + b * 8 + brow_in) * WS2_STRIDE + kk + bkq) * 2);
                mma_bf16(cb[b][0], cb[b][1], cb[b][2], cb[b][3], a0, a1, a2, a3, b0, b1);
            }
        }

        cp_wait<0>();
        __syncthreads();     // xs fully staged

#pragma unroll
        for (int b = 0; b < 2; b++) {
            const int n = np * 16 + b * 8 + tq * 2;     // local col in 64
            const int u = np * 2 + b;                   // 16B unit 0..7
            const float bb0 = b2s[n], bb1 = b2s[n + 1];
#pragma unroll
            for (int half = 0; half < 2; half++) {
                const int m = mh * 16 + quad + half * 8;
                const int bat = rA + m;
                const int col = cB + n;
                const size_t oidx = ((size_t)bat * SEQLEN + t) * HIDDEN + col;
                float2 xh = *(const float2*)(xs + m * 64 + n);
                float nv0 = tanhf(xh.x + cb[b][half * 2 + 0] + bb0);
                float nv1 = tanhf(xh.y + cb[b][half * 2 + 1] + bb1);
                bool ok = t < lns[m];
                float h0 = ok ? nv0 : hreg[b][half * 2 + 0];
                float h1 = ok ? nv1 : hreg[b][half * 2 + 1];
                hreg[b][half * 2 + 0] = h0;
                hreg[b][half * 2 + 1] = h1;
                float2 hv; hv.x = h0; hv.y = h1;
                *(float2*)(out + oidx) = hv;
                // own h chunk: [32 rows][64 cols], unit u, swizzle u^(r&7)
                unsigned short* chunk = g_h_bf16 + (size_t)(grp * 16 + mem) * 2048;
                *(unsigned*)(chunk + m * 64 + ((u ^ (m & 7)) << 3) + tq * 2) = pack_bf16(h0, h1);
            }
        }
        __threadfence();
        __syncthreads();
        if (tid == 0) g_hflag[grp][mem * 32] = (unsigned)(t + 1);
    }
}

// ---------------------------------------------------------------------------
extern "C" void kernel_launch(void* const* d_in, const int* in_sizes, int n_in,
                              void* d_out, int out_size)
{
    const float* seq  = (const float*)d_in[0];
    const int*   lens = (const int*)  d_in[1];
    const float* w1x  = (const float*)d_in[2];
    const float* b1x  = (const float*)d_in[3];
    const float* w2x  = (const float*)d_in[4];
    const float* b2x  = (const float*)d_in[5];
    const float* w1h  = (const float*)d_in[6];
    const float* b1h  = (const float*)d_in[7];
    const float* w2h  = (const float*)d_in[8];
    const float* b2h  = (const float*)d_in[9];
    float* out = (float*)d_out;

    unsigned short *a1p, *hidp, *w1xp, *w2xp;
    cudaGetSymbolAddress((void**)&a1p,  g_a1p);
    cudaGetSymbolAddress((void**)&hidp, g_hidp);
    cudaGetSymbolAddress((void**)&w1xp, g_w1xp);
    cudaGetSymbolAddress((void**)&w2xp, g_w2xp);

    static bool attr_set = false;
    if (!attr_set) {
        cudaFuncSetAttribute(recurrence_tc,
                             cudaFuncAttributeMaxDynamicSharedMemorySize, SMEM_TOTAL);
        cudaFuncSetAttribute(bgemm_kernel<true, true>,
                             cudaFuncAttributeMaxDynamicSharedMemorySize, GSMEM_TOTAL);
        cudaFuncSetAttribute(bgemm_kernel<false, false>,
                             cudaFuncAttributeMaxDynamicSharedMemorySize, GSMEM_TOTAL);
        attr_set = true;
    }

    // Pack operands (hi/lo split)
    pack_a_kernel<<<(NTOK * EMB / 4) / 256, 256>>>(seq, a1p);
    pack_w_kernel<<<(HALF_H * 512 + 255) / 256, 256>>>(w1x, w1xp, HALF_H);
    pack_w_kernel<<<(HIDDEN * 512 + 255) / 256, 256>>>(w2x, w2xp, HIDDEN);

    // K1: hidp = pack(relu(seq @ w1x + b1x))   (length-skipped)
    bgemm_kernel<true, true><<<dim3(HALF_H / 128, NTOK / 128), 256, GSMEM_TOTAL>>>(
        a1p, w1xp, b1x, nullptr, hidp, HALF_H, lens);

    // K2: out = hid @ w2x + b2x   (xh, length-skipped)
    bgemm_kernel<false, false><<<dim3(HIDDEN / 128, NTOK / 128), 256, GSMEM_TOTAL>>>(
        hidp, w2xp, b2x, out, nullptr, HIDDEN, lens);

    // K3: persistent recurrence, barrier-free dataflow sync
    recurrence_tc<<<NCTA, NTHR, SMEM_TOTAL>>>(w1h, b1h, w2h, b2h, lens, out);
}

// round 15
// speedup vs baseline: 1.1893x; 1.0333x over previous
#include <cuda_runtime.h>
#include <cuda_bf16.h>
#include <math.h>
#include <string.h>

// Problem constants (fixed by the dataset)
#define EMB     512
#define HIDDEN  1024
#define HALF_H  512
#define BATCH   256
#define SEQLEN  512
#define NTOK    (BATCH * SEQLEN)   // 131072
#define KP      1536               // 3 * 512 packed-K for split-bf16 GEMMs

#define NCTA    128
#define NTHR    256

// ---------------------------------------------------------------------------
// Device globals (allocation-free scratch)
// h / h1 exchange buffers are chunk-contiguous per producer CTA:
//   g_h_bf16 : [8 groups][16 producers][32 rows][64 cols]  (rows XOR-swizzled)
//   g_h1_bf16: [8 groups][16 producers][32 rows][32 cols]  (rows XOR-swizzled)
// ---------------------------------------------------------------------------
__device__ unsigned short g_a1p[(size_t)NTOK * KP];    // packed seq   [M][1536]
__device__ unsigned short g_hidp[(size_t)NTOK * KP];   // packed hid1  [M][1536]
__device__ unsigned short g_w1xp[HALF_H * KP];         // packed w1x   [512][1536] (n-major)
__device__ unsigned short g_w2xp[HIDDEN * KP];         // packed w2x   [1024][1536] (n-major)
__device__ unsigned short g_h_bf16[BATCH * HIDDEN];
__device__ unsigned short g_h1_bf16[BATCH * HALF_H];
__device__ volatile unsigned g_ggen[8 * 32];           // init barrier gen
__device__ unsigned g_gcnt[8 * 32];                    // init barrier count
__device__ volatile unsigned g_hflag[8][16 * 32];      // h ready flags (128B apart)
__device__ volatile unsigned g_h1flag[8][16 * 32];     // h1 ready flags

// ---------------------------------------------------------------------------
// Helpers
// ---------------------------------------------------------------------------
static __device__ __forceinline__ unsigned smem_u32(const void* p) {
    unsigned a;
    asm("{ .reg .u64 t; cvta.to.shared.u64 t, %1; cvt.u32.u64 %0, t; }"
        : "=r"(a) : "l"(p));
    return a;
}

static __device__ __forceinline__ void ldsm_x4(unsigned& r0, unsigned& r1,
                                               unsigned& r2, unsigned& r3,
                                               unsigned addr) {
    asm volatile("ldmatrix.sync.aligned.m8n8.x4.shared.b16 {%0,%1,%2,%3}, [%4];"
                 : "=r"(r0), "=r"(r1), "=r"(r2), "=r"(r3) : "r"(addr));
}

static __device__ __forceinline__ void ldsm_x2(unsigned& r0, unsigned& r1,
                                               unsigned addr) {
    asm volatile("ldmatrix.sync.aligned.m8n8.x2.shared.b16 {%0,%1}, [%2];"
                 : "=r"(r0), "=r"(r1) : "r"(addr));
}

static __device__ __forceinline__ void mma_bf16(float& c0, float& c1, float& c2, float& c3,
                                                unsigned a0, unsigned a1, unsigned a2, unsigned a3,
                                                unsigned b0, unsigned b1) {
    asm volatile("mma.sync.aligned.m16n8k16.row.col.f32.bf16.bf16.f32 "
                 "{%0,%1,%2,%3}, {%4,%5,%6,%7}, {%8,%9}, {%0,%1,%2,%3};"
                 : "+f"(c0), "+f"(c1), "+f"(c2), "+f"(c3)
                 : "r"(a0), "r"(a1), "r"(a2), "r"(a3), "r"(b0), "r"(b1));
}

static __device__ __forceinline__ unsigned pack_bf16(float x, float y) {
    __nv_bfloat162 v = __floats2bfloat162_rn(x, y);
    unsigned u;
    memcpy(&u, &v, 4);
    return u;
}

static __device__ __forceinline__ unsigned short f2bf(float x) {
    __nv_bfloat16 v = __float2bfloat16(x);
    unsigned short u;
    memcpy(&u, &v, 2);
    return u;
}

static __device__ __forceinline__ float bf2f(unsigned short u) {
    __nv_bfloat16 v;
    memcpy(&v, &u, 2);
    return __bfloat162float(v);
}

static __device__ __forceinline__ void cp16(unsigned saddr, const void* gaddr) {
    asm volatile("cp.async.cg.shared.global [%0], [%1], 16;\n"
                 :: "r"(saddr), "l"(gaddr));
}
static __device__ __forceinline__ void cp_commit() {
    asm volatile("cp.async.commit_group;\n");
}
template <int N>
static __device__ __forceinline__ void cp_wait() {
    asm volatile("cp.async.wait_group %0;\n" :: "n"(N));
}

// ---- mbarrier + 1D bulk-copy helpers ----
static __device__ __forceinline__ void mbar_init(unsigned bar, unsigned count) {
    asm volatile("mbarrier.init.shared.b64 [%0], %1;" :: "r"(bar), "r"(count) : "memory");
}
static __device__ __forceinline__ void mbar_expect(unsigned bar, unsigned bytes) {
    asm volatile("mbarrier.arrive.expect_tx.shared.b64 _, [%0], %1;"
                 :: "r"(bar), "r"(bytes) : "memory");
}
static __device__ __forceinline__ void bulk_g2s(unsigned dst, const void* src,
                                                unsigned bytes, unsigned bar) {
    asm volatile("cp.async.bulk.shared::cta.global.mbarrier::complete_tx::bytes "
                 "[%0], [%1], %2, [%3];"
                 :: "r"(dst), "l"(src), "r"(bytes), "r"(bar) : "memory");
}
static __device__ __forceinline__ void mbar_wait(unsigned bar, unsigned parity) {
    asm volatile("{\n\t"
                 ".reg .pred p;\n\t"
                 "WAIT_%=:\n\t"
                 "mbarrier.try_wait.parity.shared::cta.b64 p, [%0], %1;\n\t"
                 "@!p bra WAIT_%=;\n\t"
                 "}"
                 :: "r"(bar), "r"(parity) : "memory");
}

// Init-time software barrier (atomic, self-resetting across replays).
static __device__ __forceinline__ void groupbar(int g) {
    __threadfence();
    __syncthreads();
    if (threadIdx.x == 0) {
        const int gi = g * 32;
        unsigned gen = g_ggen[gi];
        if (atomicAdd(&g_gcnt[gi], 1) == 15) {
            g_gcnt[gi] = 0;
            __threadfence();
            g_ggen[gi] = gen + 1;
        } else {
            while (g_ggen[gi] == gen) { }
            __threadfence();
        }
    }
    __syncthreads();
}

// ---------------------------------------------------------------------------
// Packing kernels (hi/lo split, pairing baked into column order)
// ---------------------------------------------------------------------------
__global__ void pack_a_kernel(const float* __restrict__ A,
                              unsigned short* __restrict__ Ap,
                              const int* __restrict__ lens)
{
    const size_t idx  = (size_t)blockIdx.x * blockDim.x + threadIdx.x;
    const size_t base = idx * 4;
    const size_t m    = base >> 9;
    const int    k    = (int)(base & 511);

    // token-level skip: dead tokens (s >= len[b]) feed only dead output rows.
    {
        const int b = (int)(m >> 9);
        const int s = (int)(m & 511);
        if (s >= __ldg(&lens[b])) return;
    }

    const float4 v = *(const float4*)(A + base);

    unsigned short h0 = f2bf(v.x), h1 = f2bf(v.y), h2 = f2bf(v.z), h3 = f2bf(v.w);
    unsigned short l0 = f2bf(v.x - bf2f(h0));
    unsigned short l1 = f2bf(v.y - bf2f(h1));
    unsigned short l2 = f2bf(v.z - bf2f(h2));
    unsigned short l3 = f2bf(v.w - bf2f(h3));

    uint2 hv, lv;
    hv.x = (unsigned)h0 | ((unsigned)h1 << 16);
    hv.y = (unsigned)h2 | ((unsigned)h3 << 16);
    lv.x = (unsigned)l0 | ((unsigned)l1 << 16);
    lv.y = (unsigned)l2 | ((unsigned)l3 << 16);

    unsigned short* row = Ap + m * KP;
    *(uint2*)(row + k)        = hv;
    *(uint2*)(row + 512 + k)  = lv;
    *(uint2*)(row + 1024 + k) = hv;
}

__global__ void pack_w_kernel(const float* __restrict__ W,
                              unsigned short* __restrict__ Wp, int N)
{
    const int idx = blockIdx.x * blockDim.x + threadIdx.x;
    if (idx >= N * 512) return;
    const int n = idx / 512;
    const int k = idx % 512;
    const float v = W[(size_t)k * N + n];
    unsigned short hi = f2bf(v);
    unsigned short lo = f2bf(v - bf2f(hi));
    unsigned short* row = Wp + (size_t)n * KP;
    row[k]        = hi;
    row[512 + k]  = hi;
    row[1024 + k] = lo;
}

// ---------------------------------------------------------------------------
// bf16 tensor-core GEMM (round-8 proven core) + length-based tile skip.
// BM=128, BN=128, BK=32, 256 threads, 8 warps (2m x 4n), warp tile 64x32.
// ---------------------------------------------------------------------------
#define TSTRIDE 40
#define GSTAGES 4
#define GST_HALVES (128 * TSTRIDE)
#define GST_BYTES  (GST_HALVES * 2)
#define GSMEM_TOTAL (GSTAGES * GST_BYTES * 2)

template <bool RELU, bool PACK>
__global__ __launch_bounds__(256, 2)
void bgemm_kernel(const unsigned short* __restrict__ Ap,
                  const unsigned short* __restrict__ Wp,
                  const float* __restrict__ bias,
                  float* __restrict__ Cf,
                  unsigned short* __restrict__ Cp,
                  int N,
                  const int* __restrict__ lens)
{
    extern __shared__ char gsm[];
    unsigned short* As = (unsigned short*)gsm;
    unsigned short* Bs = (unsigned short*)(gsm + GSTAGES * GST_BYTES);

    const int m0 = blockIdx.y * 128;

    // length-based tile skip
    {
        const int b  = m0 >> 9;
        const int s0 = m0 & 511;
        if (s0 >= __ldg(&lens[b])) return;
    }

    const int tid  = threadIdx.x;
    const int n0   = blockIdx.x * 128;
    const int wid  = tid >> 5;
    const int lane = tid & 31;
    const int wm   = wid & 1;
    const int wn   = wid >> 1;

    const int lrow = tid >> 1;
    const int lcol = (tid & 1) * 16;
    const unsigned short* Ag = Ap + (size_t)(m0 + lrow) * KP + lcol;
    const unsigned short* Bg = Wp + (size_t)(n0 + lrow) * KP + lcol;

    const unsigned uA0 = smem_u32(As);
    const unsigned uB0 = smem_u32(Bs);
    const unsigned sa0 = uA0 + (unsigned)(lrow * TSTRIDE + lcol) * 2;
    const unsigned sb0 = uB0 + (unsigned)(lrow * TSTRIDE + lcol) * 2;

    const int aj  = lane >> 3;
    const int ar  = (aj & 1) * 8 + (lane & 7);
    const int akq = (aj >> 1) * 8;

    float acc[4][4][4];
#pragma unroll
    for (int i = 0; i < 4; i++)
#pragma unroll
        for (int j = 0; j < 4; j++)
#pragma unroll
            for (int q = 0; q < 4; q++) acc[i][j][q] = 0.0f;

#define G_ISSUE(it_) do {                                              \
        const int _buf = (it_) & (GSTAGES - 1);                        \
        const int _k0  = (it_) * 32;                                   \
        cp16(sa0 + _buf * GST_BYTES,      Ag + _k0);                   \
        cp16(sa0 + _buf * GST_BYTES + 16, Ag + _k0 + 8);               \
        cp16(sb0 + _buf * GST_BYTES,      Bg + _k0);                   \
        cp16(sb0 + _buf * GST_BYTES + 16, Bg + _k0 + 8);               \
        cp_commit();                                                   \
    } while (0)

    G_ISSUE(0); G_ISSUE(1); G_ISSUE(2);

    const int NITER = KP / 32;   // 48
    for (int it = 0; it < NITER; it++) {
        if (it < NITER - 2)       cp_wait<2>();
        else if (it == NITER - 2) cp_wait<1>();
        else                      cp_wait<0>();
        __syncthreads();
        if (it + 3 < NITER) G_ISSUE(it + 3);

        const int buf = it & (GSTAGES - 1);
        const unsigned uA = uA0 + (unsigned)buf * GST_BYTES;
        const unsigned uB = uB0 + (unsigned)buf * GST_BYTES;

#pragma unroll
        for (int kk = 0; kk < 32; kk += 16) {
            unsigned a[4][4], b[2][4];
#pragma unroll
            for (int mi = 0; mi < 4; mi++)
                ldsm_x4(a[mi][0], a[mi][1], a[mi][2], a[mi][3],
                        uA + (unsigned)((wm * 64 + mi * 16 + ar) * TSTRIDE + kk + akq) * 2);
#pragma unroll
            for (int p = 0; p < 2; p++)
                ldsm_x4(b[p][0], b[p][1], b[p][2], b[p][3],
                        uB + (unsigned)((wn * 32 + p * 16 + ar) * TSTRIDE + kk + akq) * 2);
#pragma unroll
            for (int mi = 0; mi < 4; mi++) {
#pragma unroll
                for (int p = 0; p < 2; p++) {
                    mma_bf16(acc[mi][2*p][0], acc[mi][2*p][1], acc[mi][2*p][2], acc[mi][2*p][3],
                             a[mi][0], a[mi][1], a[mi][2], a[mi][3], b[p][0], b[p][2]);
                    mma_bf16(acc[mi][2*p+1][0], acc[mi][2*p+1][1], acc[mi][2*p+1][2], acc[mi][2*p+1][3],
                             a[mi][0], a[mi][1], a[mi][2], a[mi][3], b[p][1], b[p][3]);
                }
            }
        }
    }
#undef G_ISSUE

    const int quad = lane >> 2;
    const int tq   = lane & 3;
#pragma unroll
    for (int mi = 0; mi < 4; mi++) {
#pragma unroll
        for (int ni = 0; ni < 4; ni++) {
            const int n = n0 + wn * 32 + ni * 8 + tq * 2;
            const float bb0 = bias[n], bb1 = bias[n + 1];
#pragma unroll
            for (int half = 0; half < 2; half++) {
                const int m = m0 + wm * 64 + mi * 16 + quad + half * 8;
                float v0 = acc[mi][ni][half * 2 + 0] + bb0;
                float v1 = acc[mi][ni][half * 2 + 1] + bb1;
                if (RELU) { v0 = fmaxf(v0, 0.f); v1 = fmaxf(v1, 0.f); }
                if (PACK) {
                    unsigned short h0 = f2bf(v0), h1 = f2bf(v1);
                    unsigned short l0 = f2bf(v0 - bf2f(h0));
                    unsigned short l1 = f2bf(v1 - bf2f(h1));
                    unsigned hv = (unsigned)h0 | ((unsigned)h1 << 16);
                    unsigned lv = (unsigned)l0 | ((unsigned)l1 << 16);
                    unsigned short* row = Cp + (size_t)m * KP;
                    *(unsigned*)(row + n)        = hv;
                    *(unsigned*)(row + 512 + n)  = lv;
                    *(unsigned*)(row + 1024 + n) = hv;
                } else {
                    float2 v; v.x = v0; v.y = v1;
                    *(float2*)(Cf + (size_t)m * N + n) = v;
                }
            }
        }
    }
}

// ---------------------------------------------------------------------------
// Persistent recurrence kernel: barrier-free dataflow + progressive
// sub-barriers (4 per phase) + 2-way split accumulator chains.
// ---------------------------------------------------------------------------
#define WS1_STRIDE 1032
#define WS2_STRIDE 520

#define OFF_WS1  0
#define OFF_WS2  (OFF_WS1 + 32 * WS1_STRIDE * 2)     // 66048
#define OFF_ACH  (OFF_WS2 + 64 * WS2_STRIDE * 2)     // 132608 (128B aligned)
#define OFF_H1S  (OFF_ACH + 65536)                   // 198144
#define OFF_B1   (OFF_H1S + 32768)                   // 230912
#define OFF_B2   (OFF_B1 + 32 * 4)                   // 231040
#define OFF_LEN  (OFF_B2 + 64 * 4)                   // 231296
#define OFF_MBAR (OFF_LEN + 32 * 4)                  // 231424: 8 sub-barriers
#define SMEM_TOTAL (OFF_MBAR + 8 * 8)                // 231488

__global__ __launch_bounds__(NTHR, 1)
void recurrence_tc(const float* __restrict__ W1h,
                   const float* __restrict__ b1h,
                   const float* __restrict__ W2h,
                   const float* __restrict__ b2h,
                   const int*   __restrict__ lens,
                   float* __restrict__ out)
{
    extern __shared__ char smem[];
    unsigned short* ws1 = (unsigned short*)(smem + OFF_WS1);
    unsigned short* ws2 = (unsigned short*)(smem + OFF_WS2);
    float* b1s = (float*)(smem + OFF_B1);
    float* b2s = (float*)(smem + OFF_B2);
    int*   lns = (int*)(smem + OFF_LEN);
    const float* xs = (const float*)(smem + OFF_ACH);   // xh staging (phase B)

    const unsigned u_ws1 = smem_u32(ws1);
    const unsigned u_ws2 = smem_u32(ws2);
    const unsigned u_ach = smem_u32(smem + OFF_ACH);
    const unsigned u_h1s = smem_u32(smem + OFF_H1S);
    const unsigned u_bar = smem_u32(smem + OFF_MBAR);   // A: +0..24, B: +32..56

    const int tid  = threadIdx.x;
    const int cta  = blockIdx.x;
    const int wid  = tid >> 5;
    const int lane = tid & 31;
    const int quad = lane >> 2;
    const int tq   = lane & 3;

    const int grp = cta >> 4;
    const int mem = cta & 15;
    const int rA = grp * 32;
    const int cA = mem * 32;
    const int cB = mem * 64;

    const int mh = wid & 1;
    const int nb = wid >> 1;
    const int np = wid >> 1;

    for (int i = tid; i < 1024 * 32; i += NTHR) {
        int k = i >> 5, n = i & 31;
        ws1[n * WS1_STRIDE + k] = f2bf(W1h[(size_t)k * HALF_H + cA + n]);
    }
    for (int i = tid; i < 512 * 64; i += NTHR) {
        int k = i >> 6, n = i & 63;
        ws2[n * WS2_STRIDE + k] = f2bf(W2h[(size_t)k * HIDDEN + cB + n]);
    }
    if (tid < 32) { b1s[tid] = b1h[cA + tid]; lns[tid] = lens[rA + tid]; }
    if (tid < 64) b2s[tid] = b2h[cB + tid];

    if (tid == 0) {
        for (int q = 0; q < 8; q++) mbar_init(u_bar + q * 8, 4);
        g_hflag[grp][mem * 32]  = 0; // reset own flags (replay-safe)
        g_h1flag[grp][mem * 32] = 0;
    }

    // zero own h chunk (zeros are swizzle-invariant)
    {
        unsigned* hz = (unsigned*)g_h_bf16 + (size_t)(grp * 16 + mem) * 1024;
        for (int i = tid; i < 1024; i += NTHR) hz[i] = 0u;
    }

    float hreg[2][4];
#pragma unroll
    for (int b = 0; b < 2; b++)
#pragma unroll
        for (int j = 0; j < 4; j++) hreg[b][j] = 0.0f;

    groupbar(grp);   // flags reset + zeros + mbar inits visible group-wide

    // ldmatrix lane mapping
    const int aj   = lane >> 3;
    const int arow = mh * 16 + (aj & 1) * 8 + (lane & 7);   // 0..31
    const int ku   = aj >> 1;                               // 0/1
    const int swzA = arow & 7;
    const int swzB = arow & 3;
    const int li   = lane & 15;
    const int brow_in = li & 7;
    const int bkq  = (li >> 3) * 8;

    // chunk bases in global (bytes)
    const char* ghg  = (const char*)g_h_bf16  + (size_t)grp * 16 * 4096;
    const char* gh1g = (const char*)g_h1_bf16 + (size_t)grp * 16 * 2048;

    for (int t = 0; t < SEQLEN; t++) {
        const unsigned par = (unsigned)(t & 1);

        // ============ PHASE A: h1 = relu(h @ W1h + b1) ============
        if (tid < 16) {
            while (g_hflag[grp][tid * 32] < (unsigned)t) { }
            const unsigned sb = u_bar + (unsigned)(tid >> 2) * 8;
            mbar_expect(sb, 4096);
            bulk_g2s(u_ach + (unsigned)tid * 4096, ghg + (size_t)tid * 4096,
                     4096, sb);
        }

        float ca[2][4];
#pragma unroll
        for (int p = 0; p < 2; p++)
#pragma unroll
            for (int j = 0; j < 4; j++) ca[p][j] = 0.f;

#pragma unroll
        for (int q = 0; q < 4; q++) {
            mbar_wait(u_bar + (unsigned)q * 8, par);
            float* cc = ca[q & 1];
#pragma unroll 4
            for (int kk = q * 256; kk < q * 256 + 256; kk += 16) {
                const int c  = kk >> 6;
                const int lu = ((kk & 63) >> 3) + ku;
                unsigned a0, a1, a2, a3, b0, b1;
                ldsm_x4(a0, a1, a2, a3,
                        u_ach + (unsigned)(c * 4096 + arow * 128 + ((lu ^ swzA) << 4)));
                ldsm_x2(b0, b1, u_ws1 + (unsigned)((nb * 8 + brow_in) * WS1_STRIDE + kk + bkq) * 2);
                mma_bf16(cc[0], cc[1], cc[2], cc[3], a0, a1, a2, a3, b0, b1);
            }
        }
        {
            // write own h1 chunk: [32 rows][32 cols], unit u = nb, swizzle u^(r&3)
            const int n = nb * 8 + tq * 2;
            const int m0w = mh * 16 + quad;
            float v0 = fmaxf(ca[0][0] + ca[1][0] + b1s[n], 0.f);
            float v1 = fmaxf(ca[0][1] + ca[1][1] + b1s[n + 1], 0.f);
            float v2 = fmaxf(ca[0][2] + ca[1][2] + b1s[n], 0.f);
            float v3 = fmaxf(ca[0][3] + ca[1][3] + b1s[n + 1], 0.f);
            unsigned short* chunk = g_h1_bf16 + (size_t)(grp * 16 + mem) * 1024;
            const int r0 = m0w, r1 = m0w + 8;
            *(unsigned*)(chunk + r0 * 32 + ((nb ^ (r0 & 3)) << 3) + tq * 2) = pack_bf16(v0, v1);
            *(unsigned*)(chunk + r1 * 32 + ((nb ^ (r1 & 3)) << 3) + tq * 2) = pack_bf16(v2, v3);
        }
        __threadfence();
        __syncthreads();
        if (tid == 0) g_h1flag[grp][mem * 32] = (unsigned)(t + 1);

        // ============ PHASE B: h = tanh(xh + h1 @ W2h + b2) ============
        if (tid < 16) {
            while (g_h1flag[grp][tid * 32] < (unsigned)(t + 1)) { }
            const unsigned sb = u_bar + 32 + (unsigned)(tid >> 2) * 8;
            mbar_expect(sb, 2048);
            bulk_g2s(u_h1s + (unsigned)tid * 2048, gh1g + (size_t)tid * 2048,
                     2048, sb);
        }
        // xh prefetch into (now idle) ach region: 32 rows x 64 cols f32 = 8KB
#pragma unroll
        for (int j = 0; j < 2; j++) {
            const int lin = tid * 2 + j;
            const int row = lin >> 4;
            const int u   = lin & 15;
            cp16(u_ach + (unsigned)lin * 16,
                 out + ((size_t)(rA + row) * SEQLEN + t) * HIDDEN + cB + u * 4);
        }
        cp_commit();

        float cb[2][2][4];   // [qpar][b][4]
#pragma unroll
        for (int p = 0; p < 2; p++)
#pragma unroll
            for (int b = 0; b < 2; b++)
#pragma unroll
                for (int j = 0; j < 4; j++) cb[p][b][j] = 0.f;

#pragma unroll
        for (int q = 0; q < 4; q++) {
            mbar_wait(u_bar + 32 + (unsigned)q * 8, par);
            const int qp = q & 1;
#pragma unroll 4
            for (int kk = q * 128; kk < q * 128 + 128; kk += 16) {
                const int c  = kk >> 5;
                const int lu = ((kk & 31) >> 3) + ku;
                unsigned a0, a1, a2, a3;
                ldsm_x4(a0, a1, a2, a3,
                        u_h1s + (unsigned)(c * 2048 + arow * 64 + ((lu ^ swzB) << 4)));
#pragma unroll
                for (int b = 0; b < 2; b++) {
                    unsigned b0, b1;
                    ldsm_x2(b0, b1, u_ws2 + (unsigned)((np * 16 + b * 8 + brow_in) * WS2_STRIDE + kk + bkq) * 2);
                    mma_bf16(cb[qp][b][0], cb[qp][b][1], cb[qp][b][2], cb[qp][b][3],
                             a0, a1, a2, a3, b0, b1);
                }
            }
        }

        cp_wait<0>();
        __syncthreads();     // xs fully staged

#pragma unroll
        for (int b = 0; b < 2; b++) {
            const int n = np * 16 + b * 8 + tq * 2;     // local col in 64
            const int u = np * 2 + b;                   // 16B unit 0..7
            const float bb0 = b2s[n], bb1 = b2s[n + 1];
#pragma unroll
            for (int half = 0; half < 2; half++) {
                const int m = mh * 16 + quad + half * 8;
                const int bat = rA + m;
                const int col = cB + n;
                const size_t oidx = ((size_t)bat * SEQLEN + t) * HIDDEN + col;
                float2 xh = *(const float2*)(xs + m * 64 + n);
                const float s0 = cb[0][b][half * 2 + 0] + cb[1][b][half * 2 + 0];
                const float s1 = cb[0][b][half * 2 + 1] + cb[1][b][half * 2 + 1];
                float nv0 = tanhf(xh.x + s0 + bb0);
                float nv1 = tanhf(xh.y + s1 + bb1);
                bool ok = t < lns[m];
                float h0 = ok ? nv0 : hreg[b][half * 2 + 0];
                float h1 = ok ? nv1 : hreg[b][half * 2 + 1];
                hreg[b][half * 2 + 0] = h0;
                hreg[b][half * 2 + 1] = h1;
                float2 hv; hv.x = h0; hv.y = h1;
                *(float2*)(out + oidx) = hv;
                // own h chunk: [32 rows][64 cols], unit u, swizzle u^(r&7)
                unsigned short* chunk = g_h_bf16 + (size_t)(grp * 16 + mem) * 2048;
                *(unsigned*)(chunk + m * 64 + ((u ^ (m & 7)) << 3) + tq * 2) = pack_bf16(h0, h1);
            }
        }
        __threadfence();
        __syncthreads();
        if (tid == 0) g_hflag[grp][mem * 32] = (unsigned)(t + 1);
    }
}

// ---------------------------------------------------------------------------
extern "C" void kernel_launch(void* const* d_in, const int* in_sizes, int n_in,
                              void* d_out, int out_size)
{
    const float* seq  = (const float*)d_in[0];
    const int*   lens = (const int*)  d_in[1];
    const float* w1x  = (const float*)d_in[2];
    const float* b1x  = (const float*)d_in[3];
    const float* w2x  = (const float*)d_in[4];
    const float* b2x  = (const float*)d_in[5];
    const float* w1h  = (const float*)d_in[6];
    const float* b1h  = (const float*)d_in[7];
    const float* w2h  = (const float*)d_in[8];
    const float* b2h  = (const float*)d_in[9];
    float* out = (float*)d_out;

    unsigned short *a1p, *hidp, *w1xp, *w2xp;
    cudaGetSymbolAddress((void**)&a1p,  g_a1p);
    cudaGetSymbolAddress((void**)&hidp, g_hidp);
    cudaGetSymbolAddress((void**)&w1xp, g_w1xp);
    cudaGetSymbolAddress((void**)&w2xp, g_w2xp);

    static bool attr_set = false;
    if (!attr_set) {
        cudaFuncSetAttribute(recurrence_tc,
                             cudaFuncAttributeMaxDynamicSharedMemorySize, SMEM_TOTAL);
        cudaFuncSetAttribute(bgemm_kernel<true, true>,
                             cudaFuncAttributeMaxDynamicSharedMemorySize, GSMEM_TOTAL);
        cudaFuncSetAttribute(bgemm_kernel<false, false>,
                             cudaFuncAttributeMaxDynamicSharedMemorySize, GSMEM_TOTAL);
        attr_set = true;
    }

    // Pack operands (hi/lo split)
    pack_a_kernel<<<(NTOK * EMB / 4) / 256, 256>>>(seq, a1p, lens);
    pack_w_kernel<<<(HALF_H * 512 + 255) / 256, 256>>>(w1x, w1xp, HALF_H);
    pack_w_kernel<<<(HIDDEN * 512 + 255) / 256, 256>>>(w2x, w2xp, HIDDEN);

    // K1: hidp = pack(relu(seq @ w1x + b1x))   (length-skipped)
    bgemm_kernel<true, true><<<dim3(HALF_H / 128, NTOK / 128), 256, GSMEM_TOTAL>>>(
        a1p, w1xp, b1x, nullptr, hidp, HALF_H, lens);

    // K2: out = hid @ w2x + b2x   (xh, length-skipped)
    bgemm_kernel<false, false><<<dim3(HIDDEN / 128, NTOK / 128), 256, GSMEM_TOTAL>>>(
        hidp, w2xp, b2x, out, nullptr, HIDDEN, lens);

    // K3: persistent recurrence, progressive sub-barrier dataflow
    recurrence_tc<<<NCTA, NTHR, SMEM_TOTAL>>>(w1h, b1h, w2h, b2h, lens, out);
}